// round 3
// baseline (speedup 1.0000x reference)
#include <cuda_runtime.h>
#include <cstdint>
#include <cstddef>

#define EMBED    1024
#define NHEADS   16
#define HDIM     64
#define WSIZE    256
#define NWIN     64
#define MTOT     (NWIN*WSIZE)     /* 16384 */
#define LTOT     (MTOT-1)         /* 16383 */
#define QKVN     (3*EMBED)        /* 3072  */

// Scratch (allocation-free rule: __device__ globals)
__device__ float g_qkv[(size_t)MTOT * QKVN];   // gathered-order qkv (pre-rope), [M][3][16][64]
__device__ float g_osc[(size_t)MTOT * EMBED];  // scattered attention output, [M][1024]

// ---------------------------------------------------------------------------
// SGEMM  C[m][n] = sum_k A[row(m)][k] * B[n][k] + bias[n]
//   row(m) = gidx ? gidx[m] : m ;  rows >= Avalid read as zero.
//   BM=BN=128, BK=16, 256 threads, 8x8 per thread.
// ---------------------------------------------------------------------------
__global__ void __launch_bounds__(256, 2)
sgemm_nt_kernel(const float* __restrict__ A,
                const float* __restrict__ B,
                const float* __restrict__ bias,
                float* __restrict__ C,
                const int* __restrict__ gidx,
                int Mrows, int N, int K, int Avalid)
{
    __shared__ float As[16][132];
    __shared__ float Bs[16][132];
    __shared__ int   arow[128];

    const int tid = threadIdx.x;
    const int bm  = blockIdx.y * 128;
    const int bn  = blockIdx.x * 128;

    if (tid < 128) {
        int m = bm + tid;
        int r = -1;
        if (m < Mrows) {
            r = gidx ? gidx[m] : m;
            if (r >= Avalid) r = -1;
        }
        arow[tid] = r;
    }
    __syncthreads();

    float acc[8][8];
    #pragma unroll
    for (int i = 0; i < 8; i++)
        #pragma unroll
        for (int j = 0; j < 8; j++) acc[i][j] = 0.f;

    const int tx = tid & 15;
    const int ty = tid >> 4;

    for (int k0 = 0; k0 < K; k0 += 16) {
        #pragma unroll
        for (int i = 0; i < 2; i++) {
            int idx = tid + i * 256;
            int row = idx >> 2;          // 0..127
            int kq  = (idx & 3) << 2;    // 0,4,8,12
            int r = arow[row];
            float4 v = make_float4(0.f, 0.f, 0.f, 0.f);
            if (r >= 0)
                v = *reinterpret_cast<const float4*>(&A[(size_t)r * K + k0 + kq]);
            As[kq+0][row] = v.x; As[kq+1][row] = v.y;
            As[kq+2][row] = v.z; As[kq+3][row] = v.w;

            float4 wv = *reinterpret_cast<const float4*>(&B[(size_t)(bn + row) * K + k0 + kq]);
            Bs[kq+0][row] = wv.x; Bs[kq+1][row] = wv.y;
            Bs[kq+2][row] = wv.z; Bs[kq+3][row] = wv.w;
        }
        __syncthreads();

        #pragma unroll
        for (int k = 0; k < 16; k++) {
            float a[8], b[8];
            #pragma unroll
            for (int i = 0; i < 8; i++) a[i] = As[k][ty*8 + i];
            #pragma unroll
            for (int j = 0; j < 8; j++) b[j] = Bs[k][tx*8 + j];
            #pragma unroll
            for (int i = 0; i < 8; i++)
                #pragma unroll
                for (int j = 0; j < 8; j++)
                    acc[i][j] = fmaf(a[i], b[j], acc[i][j]);
        }
        __syncthreads();
    }

    float bv[8];
    #pragma unroll
    for (int j = 0; j < 8; j++) bv[j] = bias[bn + tx*8 + j];

    #pragma unroll
    for (int i = 0; i < 8; i++) {
        int m = bm + ty*8 + i;
        if (m >= Mrows) continue;
        float* crow = &C[(size_t)m * N + bn + tx*8];
        float4 v0 = make_float4(acc[i][0]+bv[0], acc[i][1]+bv[1],
                                acc[i][2]+bv[2], acc[i][3]+bv[3]);
        float4 v1 = make_float4(acc[i][4]+bv[4], acc[i][5]+bv[5],
                                acc[i][6]+bv[6], acc[i][7]+bv[7]);
        *reinterpret_cast<float4*>(&crow[0]) = v0;
        *reinterpret_cast<float4*>(&crow[4]) = v1;
    }
}

// ---------------------------------------------------------------------------
// Windowed attention. One block per (window, head). 256 threads; thread i owns
// gathered row g = w*256+i. RoPE fused into Q/K load (rope row index = g).
// Online softmax over the 256 keys; scatter write via kv_indices.
// ---------------------------------------------------------------------------
__global__ void __launch_bounds__(256)
attn_kernel(const float* __restrict__ qkv,
            const float* __restrict__ cosb,
            const float* __restrict__ sinb,
            const int* __restrict__ kvidx,
            float* __restrict__ osc)
{
    extern __shared__ float sh[];
    float* Ks = sh;                    // [WSIZE][HDIM]
    float* Vs = sh + WSIZE * HDIM;     // [WSIZE][HDIM]

    const int w = blockIdx.x;
    const int h = blockIdx.y;
    const int i = threadIdx.x;
    const int g = w * WSIZE + i;

    const float* qrow = &qkv[(size_t)g * QKVN + h * HDIM];
    const float* krow = qrow + EMBED;
    const float* vrow = qrow + 2 * EMBED;
    const float* crow = &cosb[(size_t)g * HDIM];
    const float* srow = &sinb[(size_t)g * HDIM];

    float q[HDIM];
    float* ki = &Ks[i * HDIM];
    float* vi = &Vs[i * HDIM];
    // rope: out[d] = t[d]*c[d] - t[d+32]*s[d] ; out[d+32] = t[d+32]*c[d] + t[d]*s[d]
    // (cos/sin are [ang, ang] so c[d+32]==c[d], s[d+32]==s[d])
    #pragma unroll
    for (int d = 0; d < 32; d++) {
        float c0 = crow[d], s0 = srow[d];
        float q0 = qrow[d], q1 = qrow[d+32];
        float k0 = krow[d], k1 = krow[d+32];
        q[d]     = q0*c0 - q1*s0;
        q[d+32]  = q1*c0 + q0*s0;
        ki[d]    = k0*c0 - k1*s0;
        ki[d+32] = k1*c0 + k0*s0;
        vi[d]    = vrow[d];
        vi[d+32] = vrow[d+32];
    }
    __syncthreads();

    float m = -1e30f, l = 0.f;
    float o[HDIM];
    #pragma unroll
    for (int d = 0; d < HDIM; d++) o[d] = 0.f;

    for (int j = 0; j < WSIZE; j++) {
        const float* kj = &Ks[j * HDIM];
        float s0 = 0.f, s1 = 0.f, s2 = 0.f, s3 = 0.f;
        #pragma unroll
        for (int d = 0; d < HDIM; d += 4) {
            s0 = fmaf(q[d+0], kj[d+0], s0);
            s1 = fmaf(q[d+1], kj[d+1], s1);
            s2 = fmaf(q[d+2], kj[d+2], s2);
            s3 = fmaf(q[d+3], kj[d+3], s3);
        }
        float s = 0.125f * ((s0 + s1) + (s2 + s3));   // SCALE = 64^-0.5
        if (s > m) {
            float corr = __expf(m - s);
            m = s;
            l *= corr;
            #pragma unroll
            for (int d = 0; d < HDIM; d++) o[d] *= corr;
        }
        float p = __expf(s - m);
        l += p;
        const float* vj = &Vs[j * HDIM];
        #pragma unroll
        for (int d = 0; d < HDIM; d++)
            o[d] = fmaf(p, vj[d], o[d]);
    }

    const float inv = 1.f / l;
    float* orow = &osc[(size_t)kvidx[g] * EMBED + h * HDIM];
    #pragma unroll
    for (int d = 0; d < HDIM; d += 4) {
        float4 v = make_float4(o[d]*inv, o[d+1]*inv, o[d+2]*inv, o[d+3]*inv);
        *reinterpret_cast<float4*>(&orow[d]) = v;
    }
}

// ---------------------------------------------------------------------------
extern "C" void kernel_launch(void* const* d_in, const int* in_sizes, int n_in,
                              void* d_out, int out_size)
{
    const float* x      = (const float*)d_in[0];
    const float* qkv_w  = (const float*)d_in[1];
    const float* qkv_b  = (const float*)d_in[2];
    const float* proj_w = (const float*)d_in[3];
    const float* proj_b = (const float*)d_in[4];
    // d_in[5] = padding (zeros) — handled via Avalid zero-fill
    const float* rope_c = (const float*)d_in[6];
    const float* rope_s = (const float*)d_in[7];
    const int*   kvi    = (const int*)d_in[8];   // JAX x64 disabled -> int32
    float*       out    = (float*)d_out;

    float *qkv_buf = nullptr, *osc_buf = nullptr;
    cudaGetSymbolAddress((void**)&qkv_buf, g_qkv);
    cudaGetSymbolAddress((void**)&osc_buf, g_osc);

    // 1) QKV GEMM with fused row gather: g_qkv[g] = x[kv_idx[g]] @ qkv_w^T + b
    {
        dim3 grid(QKVN / 128, MTOT / 128);
        sgemm_nt_kernel<<<grid, 256>>>(x, qkv_w, qkv_b, qkv_buf, kvi,
                                       MTOT, QKVN, EMBED, LTOT);
    }

    // 2) Windowed attention (RoPE fused, scatter fused into epilogue)
    {
        int shmem = 2 * WSIZE * HDIM * (int)sizeof(float);   // 128 KB
        cudaFuncSetAttribute(attn_kernel,
                             cudaFuncAttributeMaxDynamicSharedMemorySize, shmem);
        dim3 grid(NWIN, NHEADS);
        attn_kernel<<<grid, WSIZE, shmem>>>(qkv_buf, rope_c, rope_s, kvi, osc_buf);
    }

    // 3) Output projection: out = g_osc[:L] @ proj_w^T + proj_b
    {
        dim3 grid(EMBED / 128, (LTOT + 127) / 128);
        sgemm_nt_kernel<<<grid, 256>>>(osc_buf, proj_w, proj_b, out, nullptr,
                                       LTOT, EMBED, EMBED, MTOT);
    }
}

// round 4
// speedup vs baseline: 2.0269x; 2.0269x over previous
#include <cuda_runtime.h>
#include <cstdint>
#include <cstddef>

#define EMBED    1024
#define NHEADS   16
#define HDIM     64
#define WSIZE    256
#define NWIN     64
#define MTOT     (NWIN*WSIZE)     /* 16384 */
#define LTOT     (MTOT-1)         /* 16383 */
#define QKVN     (3*EMBED)        /* 3072  */

// Scratch (allocation-free rule: __device__ globals)
__device__ float g_qkv[(size_t)MTOT * QKVN];   // gathered-order qkv, [M][3][16][64]
__device__ float g_osc[(size_t)MTOT * EMBED];  // scattered attention output

// ---------------------------------------------------------------------------
// tf32 tensor-core GEMM:  C[m][n] = sum_k A[row(m)][k] * B[n][k] + bias[n]
//   row(m) = gidx ? gidx[m] : m ; rows with row>=Avalid (or m>=Mrows) read 0.
//   BM=BN=128, BK=32, 256 threads (8 warps, 4x2), warp tile 32x64,
//   mma.sync m16n8k8 tf32, double-buffered smem + register prefetch.
//   Smem tiles use stride 36 floats -> conflict-free fragment LDS.
// ---------------------------------------------------------------------------
#define TSTRIDE 36
#define TILE_F  (128 * TSTRIDE)

__device__ __forceinline__ uint32_t f2tf32(float f) {
    uint32_t r;
    asm("cvt.rna.tf32.f32 %0, %1;" : "=r"(r) : "f"(f));
    return r;
}

__device__ __forceinline__ void mma_tf32(float* c, const uint32_t* a, const uint32_t* b) {
    asm volatile(
        "mma.sync.aligned.m16n8k8.row.col.f32.tf32.tf32.f32 "
        "{%0,%1,%2,%3}, {%4,%5,%6,%7}, {%8,%9}, {%0,%1,%2,%3};"
        : "+f"(c[0]), "+f"(c[1]), "+f"(c[2]), "+f"(c[3])
        : "r"(a[0]), "r"(a[1]), "r"(a[2]), "r"(a[3]), "r"(b[0]), "r"(b[1]));
}

__global__ void __launch_bounds__(256)
tf32_gemm_kernel(const float* __restrict__ A,
                 const float* __restrict__ B,
                 const float* __restrict__ bias,
                 float* __restrict__ C,
                 const int* __restrict__ gidx,
                 int Mrows, int N, int K, int Avalid)
{
    extern __shared__ float sm[];
    float* As = sm;                 // [2][128][36]
    float* Bs = sm + 2 * TILE_F;    // [2][128][36]
    __shared__ int arow[128];

    const int tid  = threadIdx.x;
    const int lane = tid & 31;
    const int wid  = tid >> 5;
    const int wm   = wid & 3;       // warp row (4)
    const int wn   = wid >> 2;      // warp col (2)
    const int bm   = blockIdx.y * 128;
    const int bn   = blockIdx.x * 128;

    if (tid < 128) {
        int m = bm + tid;
        int r = -1;
        if (m < Mrows) {
            r = gidx ? gidx[m] : m;
            if (r >= Avalid) r = -1;
        }
        arow[tid] = r;
    }
    __syncthreads();

    // copy mapping: idx in [0,1024): row = idx>>3 (0..127), kq = (idx&7)*4
    const int crow = tid >> 3;
    const int ckq  = (tid & 7) << 2;

    float4 ra[4], rb[4];

    auto load_regs = [&](int k0) {
        #pragma unroll
        for (int i = 0; i < 4; i++) {
            int row = crow + i * 32;
            int r = arow[row];
            float4 v = make_float4(0.f, 0.f, 0.f, 0.f);
            if (r >= 0)
                v = *reinterpret_cast<const float4*>(&A[(size_t)r * K + k0 + ckq]);
            ra[i] = v;
            rb[i] = *reinterpret_cast<const float4*>(&B[(size_t)(bn + row) * K + k0 + ckq]);
        }
    };

    auto store_tile = [&](int buf) {
        float* ap = As + buf * TILE_F;
        float* bp = Bs + buf * TILE_F;
        #pragma unroll
        for (int i = 0; i < 4; i++) {
            int row = crow + i * 32;
            uint32_t* a4 = reinterpret_cast<uint32_t*>(&ap[row * TSTRIDE + ckq]);
            a4[0] = f2tf32(ra[i].x); a4[1] = f2tf32(ra[i].y);
            a4[2] = f2tf32(ra[i].z); a4[3] = f2tf32(ra[i].w);
            uint32_t* b4 = reinterpret_cast<uint32_t*>(&bp[row * TSTRIDE + ckq]);
            b4[0] = f2tf32(rb[i].x); b4[1] = f2tf32(rb[i].y);
            b4[2] = f2tf32(rb[i].z); b4[3] = f2tf32(rb[i].w);
        }
    };

    float acc[2][8][4];
    #pragma unroll
    for (int mt = 0; mt < 2; mt++)
        #pragma unroll
        for (int nt = 0; nt < 8; nt++)
            #pragma unroll
            for (int i = 0; i < 4; i++) acc[mt][nt][i] = 0.f;

    const int g4 = lane >> 2;   // 0..7
    const int l4 = lane & 3;    // 0..3

    load_regs(0);
    store_tile(0);
    __syncthreads();

    const int T = K / 32;
    for (int kt = 0; kt < T; kt++) {
        if (kt + 1 < T) load_regs((kt + 1) * 32);

        const uint32_t* ap = reinterpret_cast<const uint32_t*>(As + (kt & 1) * TILE_F);
        const uint32_t* bp = reinterpret_cast<const uint32_t*>(Bs + (kt & 1) * TILE_F);

        #pragma unroll
        for (int ks = 0; ks < 4; ks++) {
            const int kk = ks * 8;
            uint32_t afr[2][4], bfr[8][2];
            #pragma unroll
            for (int mt = 0; mt < 2; mt++) {
                int row = wm * 32 + mt * 16 + g4;
                afr[mt][0] = ap[(row    ) * TSTRIDE + kk + l4];
                afr[mt][1] = ap[(row + 8) * TSTRIDE + kk + l4];
                afr[mt][2] = ap[(row    ) * TSTRIDE + kk + 4 + l4];
                afr[mt][3] = ap[(row + 8) * TSTRIDE + kk + 4 + l4];
            }
            #pragma unroll
            for (int nt = 0; nt < 8; nt++) {
                int n = wn * 64 + nt * 8 + g4;
                bfr[nt][0] = bp[n * TSTRIDE + kk + l4];
                bfr[nt][1] = bp[n * TSTRIDE + kk + 4 + l4];
            }
            #pragma unroll
            for (int mt = 0; mt < 2; mt++)
                #pragma unroll
                for (int nt = 0; nt < 8; nt++)
                    mma_tf32(acc[mt][nt], afr[mt], bfr[nt]);
        }

        if (kt + 1 < T) {
            store_tile((kt + 1) & 1);
            __syncthreads();
        }
    }

    // Epilogue: bias add + store (c0,c1 adjacent cols; c2,c3 at row+8)
    #pragma unroll
    for (int nt = 0; nt < 8; nt++) {
        int col = bn + wn * 64 + nt * 8 + l4 * 2;
        float b0 = bias[col], b1 = bias[col + 1];
        #pragma unroll
        for (int mt = 0; mt < 2; mt++) {
            int row = bm + wm * 32 + mt * 16 + g4;
            if (row < Mrows) {
                float2 v = make_float2(acc[mt][nt][0] + b0, acc[mt][nt][1] + b1);
                *reinterpret_cast<float2*>(&C[(size_t)row * N + col]) = v;
            }
            if (row + 8 < Mrows) {
                float2 v = make_float2(acc[mt][nt][2] + b0, acc[mt][nt][3] + b1);
                *reinterpret_cast<float2*>(&C[(size_t)(row + 8) * N + col]) = v;
            }
        }
    }
}

// ---------------------------------------------------------------------------
// Windowed attention. One block per (window, head). 256 threads; thread i owns
// gathered row g = w*256+i. RoPE fused into Q/K load. Online softmax; scatter
// write via kv_indices.
// ---------------------------------------------------------------------------
__global__ void __launch_bounds__(256)
attn_kernel(const float* __restrict__ qkv,
            const float* __restrict__ cosb,
            const float* __restrict__ sinb,
            const int* __restrict__ kvidx,
            float* __restrict__ osc)
{
    extern __shared__ float sh[];
    float* Ks = sh;                    // [WSIZE][HDIM]
    float* Vs = sh + WSIZE * HDIM;     // [WSIZE][HDIM]

    const int w = blockIdx.x;
    const int h = blockIdx.y;
    const int i = threadIdx.x;
    const int g = w * WSIZE + i;

    const float* qrow = &qkv[(size_t)g * QKVN + h * HDIM];
    const float* krow = qrow + EMBED;
    const float* vrow = qrow + 2 * EMBED;
    const float* crow = &cosb[(size_t)g * HDIM];
    const float* srow = &sinb[(size_t)g * HDIM];

    float q[HDIM];
    float* ki = &Ks[i * HDIM];
    float* vi = &Vs[i * HDIM];
    #pragma unroll
    for (int d = 0; d < 32; d++) {
        float c0 = crow[d], s0 = srow[d];
        float q0 = qrow[d], q1 = qrow[d+32];
        float k0 = krow[d], k1 = krow[d+32];
        q[d]     = q0*c0 - q1*s0;
        q[d+32]  = q1*c0 + q0*s0;
        ki[d]    = k0*c0 - k1*s0;
        ki[d+32] = k1*c0 + k0*s0;
        vi[d]    = vrow[d];
        vi[d+32] = vrow[d+32];
    }
    __syncthreads();

    float m = -1e30f, l = 0.f;
    float o[HDIM];
    #pragma unroll
    for (int d = 0; d < HDIM; d++) o[d] = 0.f;

    for (int j = 0; j < WSIZE; j++) {
        const float* kj = &Ks[j * HDIM];
        float s0 = 0.f, s1 = 0.f, s2 = 0.f, s3 = 0.f;
        #pragma unroll
        for (int d = 0; d < HDIM; d += 4) {
            s0 = fmaf(q[d+0], kj[d+0], s0);
            s1 = fmaf(q[d+1], kj[d+1], s1);
            s2 = fmaf(q[d+2], kj[d+2], s2);
            s3 = fmaf(q[d+3], kj[d+3], s3);
        }
        float s = 0.125f * ((s0 + s1) + (s2 + s3));   // SCALE = 64^-0.5
        if (s > m) {
            float corr = __expf(m - s);
            m = s;
            l *= corr;
            #pragma unroll
            for (int d = 0; d < HDIM; d++) o[d] *= corr;
        }
        float p = __expf(s - m);
        l += p;
        const float* vj = &Vs[j * HDIM];
        #pragma unroll
        for (int d = 0; d < HDIM; d++)
            o[d] = fmaf(p, vj[d], o[d]);
    }

    const float inv = 1.f / l;
    float* orow = &osc[(size_t)kvidx[g] * EMBED + h * HDIM];
    #pragma unroll
    for (int d = 0; d < HDIM; d += 4) {
        float4 v = make_float4(o[d]*inv, o[d+1]*inv, o[d+2]*inv, o[d+3]*inv);
        *reinterpret_cast<float4*>(&orow[d]) = v;
    }
}

// ---------------------------------------------------------------------------
extern "C" void kernel_launch(void* const* d_in, const int* in_sizes, int n_in,
                              void* d_out, int out_size)
{
    const float* x      = (const float*)d_in[0];
    const float* qkv_w  = (const float*)d_in[1];
    const float* qkv_b  = (const float*)d_in[2];
    const float* proj_w = (const float*)d_in[3];
    const float* proj_b = (const float*)d_in[4];
    // d_in[5] = padding (zeros) — handled via Avalid zero-fill
    const float* rope_c = (const float*)d_in[6];
    const float* rope_s = (const float*)d_in[7];
    const int*   kvi    = (const int*)d_in[8];   // int32 indices
    float*       out    = (float*)d_out;

    float *qkv_buf = nullptr, *osc_buf = nullptr;
    cudaGetSymbolAddress((void**)&qkv_buf, g_qkv);
    cudaGetSymbolAddress((void**)&osc_buf, g_osc);

    const int gemm_smem = 4 * TILE_F * (int)sizeof(float);  // 73728 B
    cudaFuncSetAttribute(tf32_gemm_kernel,
                         cudaFuncAttributeMaxDynamicSharedMemorySize, gemm_smem);

    // 1) QKV GEMM with fused row gather: g_qkv[g] = x[kv_idx[g]] @ qkv_w^T + b
    {
        dim3 grid(QKVN / 128, MTOT / 128);
        tf32_gemm_kernel<<<grid, 256, gemm_smem>>>(x, qkv_w, qkv_b, qkv_buf, kvi,
                                                   MTOT, QKVN, EMBED, LTOT);
    }

    // 2) Windowed attention (RoPE fused, scatter fused into epilogue)
    {
        int shmem = 2 * WSIZE * HDIM * (int)sizeof(float);   // 128 KB
        cudaFuncSetAttribute(attn_kernel,
                             cudaFuncAttributeMaxDynamicSharedMemorySize, shmem);
        dim3 grid(NWIN, NHEADS);
        attn_kernel<<<grid, WSIZE, shmem>>>(qkv_buf, rope_c, rope_s, kvi, osc_buf);
    }

    // 3) Output projection: out = g_osc[:L] @ proj_w^T + proj_b
    {
        dim3 grid(EMBED / 128, (LTOT + 127) / 128);
        tf32_gemm_kernel<<<grid, 256, gemm_smem>>>(osc_buf, proj_w, proj_b, out, nullptr,
                                                   LTOT, EMBED, EMBED, MTOT);
    }
}

// round 5
// speedup vs baseline: 2.5775x; 1.2716x over previous
#include <cuda_runtime.h>
#include <cstdint>
#include <cstddef>

#define EMBED    1024
#define NHEADS   16
#define HDIM     64
#define WSIZE    256
#define NWIN     64
#define MTOT     (NWIN*WSIZE)     /* 16384 */
#define LTOT     (MTOT-1)         /* 16383 */
#define QKVN     (3*EMBED)        /* 3072  */

// Scratch (allocation-free rule: __device__ globals)
__device__ float g_qkv[(size_t)MTOT * QKVN];   // gathered-order qkv, [M][3][16][64]
__device__ float g_osc[(size_t)MTOT * EMBED];  // scattered attention output

__device__ __forceinline__ uint32_t f2tf32(float f) {
    uint32_t r;
    asm("cvt.rna.tf32.f32 %0, %1;" : "=r"(r) : "f"(f));
    return r;
}
__device__ __forceinline__ float ex2f(float x) {
    float y;
    asm("ex2.approx.f32 %0, %1;" : "=f"(y) : "f"(x));
    return y;
}
__device__ __forceinline__ void mma_tf32(float* c, const uint32_t* a, const uint32_t* b) {
    asm volatile(
        "mma.sync.aligned.m16n8k8.row.col.f32.tf32.tf32.f32 "
        "{%0,%1,%2,%3}, {%4,%5,%6,%7}, {%8,%9}, {%0,%1,%2,%3};"
        : "+f"(c[0]), "+f"(c[1]), "+f"(c[2]), "+f"(c[3])
        : "r"(a[0]), "r"(a[1]), "r"(a[2]), "r"(a[3]), "r"(b[0]), "r"(b[1]));
}

// ---------------------------------------------------------------------------
// tf32 tensor-core GEMM:  C[m][n] = sum_k A[row(m)][k] * B[n][k] + bias[n]
//   BM=BN=128, BK=32, 256 threads (8 warps, 4x2), warp tile 32x64.
//   launch_bounds(256,2): cap regs at 128 so 2 blocks/SM reside.
// ---------------------------------------------------------------------------
#define TSTRIDE 36
#define TILE_F  (128 * TSTRIDE)

__global__ void __launch_bounds__(256, 2)
tf32_gemm_kernel(const float* __restrict__ A,
                 const float* __restrict__ B,
                 const float* __restrict__ bias,
                 float* __restrict__ C,
                 const int* __restrict__ gidx,
                 int Mrows, int N, int K, int Avalid)
{
    extern __shared__ float sm[];
    float* As = sm;                 // [2][128][36]
    float* Bs = sm + 2 * TILE_F;    // [2][128][36]
    __shared__ int arow[128];

    const int tid  = threadIdx.x;
    const int lane = tid & 31;
    const int wid  = tid >> 5;
    const int wm   = wid & 3;
    const int wn   = wid >> 2;
    const int bm   = blockIdx.y * 128;
    const int bn   = blockIdx.x * 128;

    if (tid < 128) {
        int m = bm + tid;
        int r = -1;
        if (m < Mrows) {
            r = gidx ? gidx[m] : m;
            if (r >= Avalid) r = -1;
        }
        arow[tid] = r;
    }
    __syncthreads();

    const int crow = tid >> 3;
    const int ckq  = (tid & 7) << 2;

    float4 ra[4], rb[4];

    auto load_regs = [&](int k0) {
        #pragma unroll
        for (int i = 0; i < 4; i++) {
            int row = crow + i * 32;
            int r = arow[row];
            float4 v = make_float4(0.f, 0.f, 0.f, 0.f);
            if (r >= 0)
                v = *reinterpret_cast<const float4*>(&A[(size_t)r * K + k0 + ckq]);
            ra[i] = v;
            rb[i] = *reinterpret_cast<const float4*>(&B[(size_t)(bn + row) * K + k0 + ckq]);
        }
    };

    auto store_tile = [&](int buf) {
        float* ap = As + buf * TILE_F;
        float* bp = Bs + buf * TILE_F;
        #pragma unroll
        for (int i = 0; i < 4; i++) {
            int row = crow + i * 32;
            uint32_t* a4 = reinterpret_cast<uint32_t*>(&ap[row * TSTRIDE + ckq]);
            a4[0] = f2tf32(ra[i].x); a4[1] = f2tf32(ra[i].y);
            a4[2] = f2tf32(ra[i].z); a4[3] = f2tf32(ra[i].w);
            uint32_t* b4 = reinterpret_cast<uint32_t*>(&bp[row * TSTRIDE + ckq]);
            b4[0] = f2tf32(rb[i].x); b4[1] = f2tf32(rb[i].y);
            b4[2] = f2tf32(rb[i].z); b4[3] = f2tf32(rb[i].w);
        }
    };

    float acc[2][8][4];
    #pragma unroll
    for (int mt = 0; mt < 2; mt++)
        #pragma unroll
        for (int nt = 0; nt < 8; nt++)
            #pragma unroll
            for (int i = 0; i < 4; i++) acc[mt][nt][i] = 0.f;

    const int g4 = lane >> 2;
    const int l4 = lane & 3;

    load_regs(0);
    store_tile(0);
    __syncthreads();

    const int T = K / 32;
    for (int kt = 0; kt < T; kt++) {
        if (kt + 1 < T) load_regs((kt + 1) * 32);

        const uint32_t* ap = reinterpret_cast<const uint32_t*>(As + (kt & 1) * TILE_F);
        const uint32_t* bp = reinterpret_cast<const uint32_t*>(Bs + (kt & 1) * TILE_F);

        #pragma unroll
        for (int ks = 0; ks < 4; ks++) {
            const int kk = ks * 8;
            uint32_t afr[2][4], bfr[8][2];
            #pragma unroll
            for (int mt = 0; mt < 2; mt++) {
                int row = wm * 32 + mt * 16 + g4;
                afr[mt][0] = ap[(row    ) * TSTRIDE + kk + l4];
                afr[mt][1] = ap[(row + 8) * TSTRIDE + kk + l4];
                afr[mt][2] = ap[(row    ) * TSTRIDE + kk + 4 + l4];
                afr[mt][3] = ap[(row + 8) * TSTRIDE + kk + 4 + l4];
            }
            #pragma unroll
            for (int nt = 0; nt < 8; nt++) {
                int n = wn * 64 + nt * 8 + g4;
                bfr[nt][0] = bp[n * TSTRIDE + kk + l4];
                bfr[nt][1] = bp[n * TSTRIDE + kk + 4 + l4];
            }
            #pragma unroll
            for (int mt = 0; mt < 2; mt++)
                #pragma unroll
                for (int nt = 0; nt < 8; nt++)
                    mma_tf32(acc[mt][nt], afr[mt], bfr[nt]);
        }

        if (kt + 1 < T) {
            store_tile((kt + 1) & 1);
            __syncthreads();
        }
    }

    #pragma unroll
    for (int nt = 0; nt < 8; nt++) {
        int col = bn + wn * 64 + nt * 8 + l4 * 2;
        float b0 = bias[col], b1 = bias[col + 1];
        #pragma unroll
        for (int mt = 0; mt < 2; mt++) {
            int row = bm + wm * 32 + mt * 16 + g4;
            if (row < Mrows) {
                float2 v = make_float2(acc[mt][nt][0] + b0, acc[mt][nt][1] + b1);
                *reinterpret_cast<float2*>(&C[(size_t)row * N + col]) = v;
            }
            if (row + 8 < Mrows) {
                float2 v = make_float2(acc[mt][nt][2] + b0, acc[mt][nt][3] + b1);
                *reinterpret_cast<float2*>(&C[(size_t)(row + 8) * N + col]) = v;
            }
        }
    }
}

// ---------------------------------------------------------------------------
// Tensor-core flash attention. One block per (window, head); 8 warps.
// Smem (tf32 bits): Ks[256][68] roped-K, Vt[64][260] V^T, Pb[256][68]
// (Q staging, then per-warp P). Warp q owns Q rows [q*32, q*32+32).
// Online softmax in log2 domain (ex2.approx only).
// ---------------------------------------------------------------------------
#define KS_STR 68
#define VT_STR 260
#define PB_STR 68
#define KS_OFF 0
#define VT_OFF (WSIZE * KS_STR)            /* 17408 */
#define PB_OFF (VT_OFF + HDIM * VT_STR)    /* 34048 */
#define ATTN_SMEM_F (PB_OFF + WSIZE * PB_STR)  /* 51456 floats = 205824 B */

__global__ void __launch_bounds__(256)
attn_tc_kernel(const float* __restrict__ qkv,
               const float* __restrict__ cosb,
               const float* __restrict__ sinb,
               const int* __restrict__ kvidx,
               float* __restrict__ osc)
{
    extern __shared__ float shf[];
    uint32_t* sh = reinterpret_cast<uint32_t*>(shf);
    uint32_t* Ks = sh + KS_OFF;
    uint32_t* Vt = sh + VT_OFF;
    uint32_t* Pb = sh + PB_OFF;

    const int w    = blockIdx.x;
    const int h    = blockIdx.y;
    const int tid  = threadIdx.x;
    const int lane = tid & 31;
    const int wid  = tid >> 5;
    const int g4   = lane >> 2;
    const int l4   = lane & 3;
    const int wrow = wid * 32;
    const int gi   = w * WSIZE + tid;

    // ---- stage roped K, V^T, roped Q (into Pb) as tf32 ----
    {
        const float* qrow = &qkv[(size_t)gi * QKVN + h * HDIM];
        const float* krow = qrow + EMBED;
        const float* vrow = qrow + 2 * EMBED;
        const float* crw  = &cosb[(size_t)gi * HDIM];
        const float* srw  = &sinb[(size_t)gi * HDIM];
        #pragma unroll
        for (int d = 0; d < 32; d++) {
            float c0 = crw[d], s0 = srw[d];
            float q0 = qrow[d], q1 = qrow[d+32];
            float k0 = krow[d], k1 = krow[d+32];
            Pb[tid * PB_STR + d]      = f2tf32(q0*c0 - q1*s0);
            Pb[tid * PB_STR + d + 32] = f2tf32(q1*c0 + q0*s0);
            Ks[tid * KS_STR + d]      = f2tf32(k0*c0 - k1*s0);
            Ks[tid * KS_STR + d + 32] = f2tf32(k1*c0 + k0*s0);
            Vt[(d)      * VT_STR + tid] = f2tf32(vrow[d]);
            Vt[(d + 32) * VT_STR + tid] = f2tf32(vrow[d+32]);
        }
    }
    __syncthreads();

    // ---- load Q fragments (A-frags m16k8) from Pb ----
    uint32_t aQ[2][8][4];
    #pragma unroll
    for (int mt = 0; mt < 2; mt++) {
        int r0 = wrow + mt * 16 + g4;
        #pragma unroll
        for (int k8 = 0; k8 < 8; k8++) {
            aQ[mt][k8][0] = Pb[(r0    ) * PB_STR + k8*8 + l4];
            aQ[mt][k8][1] = Pb[(r0 + 8) * PB_STR + k8*8 + l4];
            aQ[mt][k8][2] = Pb[(r0    ) * PB_STR + k8*8 + 4 + l4];
            aQ[mt][k8][3] = Pb[(r0 + 8) * PB_STR + k8*8 + 4 + l4];
        }
    }
    __syncwarp();

    const float SC = 0.125f * 1.4426950408889634f;   // scale * log2(e)

    float mx[2][2], lsum[2][2];
    float Oacc[2][8][4];
    #pragma unroll
    for (int mt = 0; mt < 2; mt++)
        #pragma unroll
        for (int hf = 0; hf < 2; hf++) { mx[mt][hf] = -1e30f; lsum[mt][hf] = 0.f; }
    #pragma unroll
    for (int mt = 0; mt < 2; mt++)
        #pragma unroll
        for (int nt = 0; nt < 8; nt++)
            #pragma unroll
            for (int i = 0; i < 4; i++) Oacc[mt][nt][i] = 0.f;

    for (int c = 0; c < 4; c++) {
        const int n0 = c * 64;

        // ---- S = Q K^T chunk [32 x 64] ----
        float Sacc[2][8][4];
        #pragma unroll
        for (int mt = 0; mt < 2; mt++)
            #pragma unroll
            for (int nt = 0; nt < 8; nt++)
                #pragma unroll
                for (int i = 0; i < 4; i++) Sacc[mt][nt][i] = 0.f;

        #pragma unroll
        for (int k8 = 0; k8 < 8; k8++) {
            uint32_t bf[8][2];
            #pragma unroll
            for (int nt = 0; nt < 8; nt++) {
                int n = n0 + nt * 8 + g4;
                bf[nt][0] = Ks[n * KS_STR + k8*8 + l4];
                bf[nt][1] = Ks[n * KS_STR + k8*8 + 4 + l4];
            }
            #pragma unroll
            for (int mt = 0; mt < 2; mt++)
                #pragma unroll
                for (int nt = 0; nt < 8; nt++)
                    mma_tf32(Sacc[mt][nt], aQ[mt][k8], bf[nt]);
        }

        // ---- online softmax (log2 domain) ----
        float corr[2][2];
        #pragma unroll
        for (int mt = 0; mt < 2; mt++) {
            #pragma unroll
            for (int hf = 0; hf < 2; hf++) {
                float rm = -1e30f;
                #pragma unroll
                for (int nt = 0; nt < 8; nt++) {
                    rm = fmaxf(rm, Sacc[mt][nt][2*hf]);
                    rm = fmaxf(rm, Sacc[mt][nt][2*hf+1]);
                }
                rm = fmaxf(rm, __shfl_xor_sync(0xffffffffu, rm, 1));
                rm = fmaxf(rm, __shfl_xor_sync(0xffffffffu, rm, 2));
                float nmx = fmaxf(mx[mt][hf], rm * SC);
                corr[mt][hf] = ex2f(mx[mt][hf] - nmx);
                mx[mt][hf] = nmx;

                float ps = 0.f;
                #pragma unroll
                for (int nt = 0; nt < 8; nt++) {
                    float p0 = ex2f(fmaf(Sacc[mt][nt][2*hf],   SC, -nmx));
                    float p1 = ex2f(fmaf(Sacc[mt][nt][2*hf+1], SC, -nmx));
                    ps += p0 + p1;
                    Sacc[mt][nt][2*hf]   = p0;
                    Sacc[mt][nt][2*hf+1] = p1;
                }
                ps += __shfl_xor_sync(0xffffffffu, ps, 1);
                ps += __shfl_xor_sync(0xffffffffu, ps, 2);
                lsum[mt][hf] = lsum[mt][hf] * corr[mt][hf] + ps;

                #pragma unroll
                for (int nt = 0; nt < 8; nt++) {
                    Oacc[mt][nt][2*hf]   *= corr[mt][hf];
                    Oacc[mt][nt][2*hf+1] *= corr[mt][hf];
                }
            }
        }

        // ---- write P (tf32) to per-warp Pb region ----
        #pragma unroll
        for (int mt = 0; mt < 2; mt++) {
            int r0 = wrow + mt * 16 + g4;
            #pragma unroll
            for (int nt = 0; nt < 8; nt++) {
                int col = nt * 8 + 2 * l4;
                Pb[(r0    ) * PB_STR + col    ] = f2tf32(Sacc[mt][nt][0]);
                Pb[(r0    ) * PB_STR + col + 1] = f2tf32(Sacc[mt][nt][1]);
                Pb[(r0 + 8) * PB_STR + col    ] = f2tf32(Sacc[mt][nt][2]);
                Pb[(r0 + 8) * PB_STR + col + 1] = f2tf32(Sacc[mt][nt][3]);
            }
        }
        __syncwarp();

        // ---- O += P V chunk ----
        #pragma unroll
        for (int k8 = 0; k8 < 8; k8++) {
            uint32_t aP[2][4];
            #pragma unroll
            for (int mt = 0; mt < 2; mt++) {
                int r0 = wrow + mt * 16 + g4;
                aP[mt][0] = Pb[(r0    ) * PB_STR + k8*8 + l4];
                aP[mt][1] = Pb[(r0 + 8) * PB_STR + k8*8 + l4];
                aP[mt][2] = Pb[(r0    ) * PB_STR + k8*8 + 4 + l4];
                aP[mt][3] = Pb[(r0 + 8) * PB_STR + k8*8 + 4 + l4];
            }
            uint32_t bv[8][2];
            #pragma unroll
            for (int nt = 0; nt < 8; nt++) {
                int n = nt * 8 + g4;
                bv[nt][0] = Vt[n * VT_STR + n0 + k8*8 + l4];
                bv[nt][1] = Vt[n * VT_STR + n0 + k8*8 + 4 + l4];
            }
            #pragma unroll
            for (int mt = 0; mt < 2; mt++)
                #pragma unroll
                for (int nt = 0; nt < 8; nt++)
                    mma_tf32(Oacc[mt][nt], aP[mt], bv[nt]);
        }
        __syncwarp();
    }

    // ---- epilogue: normalize + scattered store ----
    #pragma unroll
    for (int mt = 0; mt < 2; mt++) {
        int r0 = wrow + mt * 16 + g4;
        float inv0 = 1.f / lsum[mt][0];
        float inv1 = 1.f / lsum[mt][1];
        int o0 = kvidx[w * WSIZE + r0];
        int o1 = kvidx[w * WSIZE + r0 + 8];
        float* base0 = &osc[(size_t)o0 * EMBED + h * HDIM];
        float* base1 = &osc[(size_t)o1 * EMBED + h * HDIM];
        #pragma unroll
        for (int nt = 0; nt < 8; nt++) {
            int col = nt * 8 + 2 * l4;
            float2 v0 = make_float2(Oacc[mt][nt][0] * inv0, Oacc[mt][nt][1] * inv0);
            float2 v1 = make_float2(Oacc[mt][nt][2] * inv1, Oacc[mt][nt][3] * inv1);
            *reinterpret_cast<float2*>(&base0[col]) = v0;
            *reinterpret_cast<float2*>(&base1[col]) = v1;
        }
    }
}

// ---------------------------------------------------------------------------
extern "C" void kernel_launch(void* const* d_in, const int* in_sizes, int n_in,
                              void* d_out, int out_size)
{
    const float* x      = (const float*)d_in[0];
    const float* qkv_w  = (const float*)d_in[1];
    const float* qkv_b  = (const float*)d_in[2];
    const float* proj_w = (const float*)d_in[3];
    const float* proj_b = (const float*)d_in[4];
    const float* rope_c = (const float*)d_in[6];
    const float* rope_s = (const float*)d_in[7];
    const int*   kvi    = (const int*)d_in[8];
    float*       out    = (float*)d_out;

    float *qkv_buf = nullptr, *osc_buf = nullptr;
    cudaGetSymbolAddress((void**)&qkv_buf, g_qkv);
    cudaGetSymbolAddress((void**)&osc_buf, g_osc);

    const int gemm_smem = 4 * TILE_F * (int)sizeof(float);
    cudaFuncSetAttribute(tf32_gemm_kernel,
                         cudaFuncAttributeMaxDynamicSharedMemorySize, gemm_smem);

    // 1) QKV GEMM with fused row gather
    {
        dim3 grid(QKVN / 128, MTOT / 128);
        tf32_gemm_kernel<<<grid, 256, gemm_smem>>>(x, qkv_w, qkv_b, qkv_buf, kvi,
                                                   MTOT, QKVN, EMBED, LTOT);
    }

    // 2) Tensor-core flash attention (RoPE + scatter fused)
    {
        int shmem = ATTN_SMEM_F * (int)sizeof(float);   // 205824 B
        cudaFuncSetAttribute(attn_tc_kernel,
                             cudaFuncAttributeMaxDynamicSharedMemorySize, shmem);
        dim3 grid(NWIN, NHEADS);
        attn_tc_kernel<<<grid, WSIZE, shmem>>>(qkv_buf, rope_c, rope_s, kvi, osc_buf);
    }

    // 3) Output projection
    {
        dim3 grid(EMBED / 128, (LTOT + 127) / 128);
        tf32_gemm_kernel<<<grid, 256, gemm_smem>>>(osc_buf, proj_w, proj_b, out, nullptr,
                                                   LTOT, EMBED, EMBED, MTOT);
    }
}